// round 13
// baseline (speedup 1.0000x reference)
#include <cuda_runtime.h>
#include <cstdint>

#define SQ_ 0.09016844005556022f   // (1/16)*log2(e)

static __device__ float g_Q [18874368];   // [g][s][d]  scaled by SQ_, tf32-rounded
static __device__ float g_K [18874368];   // [g][s][d]  tf32-rounded
static __device__ float g_Vt[18874368];   // [g][e][s]  tf32-rounded

__device__ __forceinline__ uint32_t smem_u32(const void* p) {
    uint32_t a;
    asm("{ .reg .u64 t; cvta.to.shared.u64 t, %1; cvt.u32.u64 %0, t; }" : "=r"(a) : "l"(p));
    return a;
}
__device__ __forceinline__ void cpa16(uint32_t d, const void* s) {
    asm volatile("cp.async.cg.shared.global [%0], [%1], 16;\n" :: "r"(d), "l"(s));
}
#define CP_COMMIT  asm volatile("cp.async.commit_group;\n" ::: "memory")
#define CP_WAIT(n) asm volatile("cp.async.wait_group %0;\n" :: "n"(n) : "memory")

__device__ __forceinline__ uint32_t f2tf(float x) {
    uint32_t u; asm("cvt.rna.tf32.f32 %0, %1;" : "=r"(u) : "f"(x)); return u;
}
__device__ __forceinline__ float ex2f(float x) {
    float y; asm("ex2.approx.ftz.f32 %0, %1;" : "=f"(y) : "f"(x)); return y;
}
__device__ __forceinline__ void mma8(float* c, const uint32_t* a, const uint32_t b0, const uint32_t b1) {
    asm volatile("mma.sync.aligned.m16n8k8.row.col.f32.tf32.tf32.f32 "
                 "{%0,%1,%2,%3}, {%4,%5,%6,%7}, {%8,%9}, {%0,%1,%2,%3};\n"
                 : "+f"(c[0]), "+f"(c[1]), "+f"(c[2]), "+f"(c[3])
                 : "r"(a[0]), "r"(a[1]), "r"(a[2]), "r"(a[3]), "r"(b0), "r"(b1));
}
__device__ __forceinline__ void ldsm4(uint32_t* r, uint32_t addr) {
    asm volatile("ldmatrix.sync.aligned.m8n8.x4.shared.b16 {%0,%1,%2,%3}, [%4];"
                 : "=r"(r[0]), "=r"(r[1]), "=r"(r[2]), "=r"(r[3]) : "r"(addr));
}

// ============================================================
// QKV (unchanged, proven): CTA 128x128, 256 thr, 3-stage cp.async ring.
// Outputs tf32-rounded; Q pre-scaled; V transposed.
// ============================================================
#define QKV_SMEM 110592

__global__ void __launch_bounds__(256, 2)
qkv_mma(const float* __restrict__ x,
        const float* __restrict__ Wq, const float* __restrict__ bq,
        const float* __restrict__ Wk, const float* __restrict__ bk,
        const float* __restrict__ Wv, const float* __restrict__ bv)
{
    extern __shared__ float smf[];
    float* As = smf;            // 3 x 4608
    float* Bs = smf + 13824;    // 3 x 4608

    const int tile = blockIdx.x, g = blockIdx.y, z = blockIdx.z;
    const int tm = tile >> 1, tn = tile & 1;
    const int hh = g % 3;
    const int tid = threadIdx.x, wid = tid >> 5, lane = tid & 31;
    const int ty = lane >> 2, tx = lane & 3;
    const int warpM = wid >> 1, warpN = wid & 1;
    const int rb = warpM * 32, nb = warpN * 64;

    const float* W; const float* bias;
    if (z == 0)      { W = Wq; bias = bq; }
    else if (z == 1) { W = Wk; bias = bk; }
    else             { W = Wv; bias = bv; }
    W += hh * 65536;  bias += hh * 256;

    const float* X  = x + ((size_t)((g / 3) * 1024 + tm * 128)) * 768 + hh * 256;
    const float* Wp = W + tn * 128 * 256;
    const uint32_t sA = smem_u32(As), sB = smem_u32(Bs);

    auto stage = [&](int dc_) {
        if (dc_ >= 8) return;
        const int bf_ = dc_ % 3;
        uint32_t dA = sA + bf_ * 18432, dB = sB + bf_ * 18432;
#pragma unroll
        for (int it = 0; it < 4; it++) {
            int i = tid + it * 256, r = i >> 3, c4 = i & 7;
            cpa16(dA + r * 144 + c4 * 16, X  + (size_t)r * 768 + dc_ * 32 + c4 * 4);
            cpa16(dB + r * 144 + c4 * 16, Wp + r * 256 + dc_ * 32 + c4 * 4);
        }
        CP_COMMIT;
    };

    float acc[2][8][4];
#pragma unroll
    for (int mf = 0; mf < 2; mf++)
#pragma unroll
        for (int nf = 0; nf < 8; nf++)
#pragma unroll
            for (int k = 0; k < 4; k++) acc[mf][nf][k] = 0.f;

    stage(0); stage(1);
#pragma unroll 1
    for (int dc = 0; dc < 8; dc++) {
        const int bf = dc % 3;
        CP_WAIT(1);
        __syncthreads();
        stage(dc + 2);
        const float* Aq = As + bf * 4608;
        const float* Bk = Bs + bf * 4608;
#pragma unroll
        for (int ks = 0; ks < 4; ks++) {
            uint32_t af[2][4], bfr[8][2];
            const int kc = ks * 8 + tx;
#pragma unroll
            for (int mf = 0; mf < 2; mf++) {
                const float* ap = Aq + (rb + mf * 16 + ty) * 36 + kc;
                af[mf][0] = f2tf(ap[0]);
                af[mf][1] = f2tf(ap[8 * 36]);
                af[mf][2] = f2tf(ap[4]);
                af[mf][3] = f2tf(ap[8 * 36 + 4]);
            }
#pragma unroll
            for (int nf = 0; nf < 8; nf++) {
                const float* bp = Bk + (nb + nf * 8 + ty) * 36 + kc;
                bfr[nf][0] = f2tf(bp[0]);
                bfr[nf][1] = f2tf(bp[4]);
            }
#pragma unroll
            for (int mf = 0; mf < 2; mf++)
#pragma unroll
                for (int nf = 0; nf < 8; nf++)
                    mma8(acc[mf][nf], af[mf], bfr[nf][0], bfr[nf][1]);
        }
    }

    if (z < 2) {
        float* dst = (z == 0 ? g_Q : g_K) + (size_t)g * 262144;
        const float osc = (z == 0) ? SQ_ : 1.0f;
#pragma unroll
        for (int mf = 0; mf < 2; mf++) {
            const int r0 = tm * 128 + rb + mf * 16 + ty, r1 = r0 + 8;
#pragma unroll
            for (int nf = 0; nf < 8; nf++) {
                const int ccol = tn * 128 + nb + nf * 8 + tx * 2;
                const float b0 = __ldg(&bias[ccol]), b1 = __ldg(&bias[ccol + 1]);
                *(float2*)&dst[(size_t)r0 * 256 + ccol] = make_float2(
                    __uint_as_float(f2tf((acc[mf][nf][0] + b0) * osc)),
                    __uint_as_float(f2tf((acc[mf][nf][1] + b1) * osc)));
                *(float2*)&dst[(size_t)r1 * 256 + ccol] = make_float2(
                    __uint_as_float(f2tf((acc[mf][nf][2] + b0) * osc)),
                    __uint_as_float(f2tf((acc[mf][nf][3] + b1) * osc)));
            }
        }
    } else {
        float* dst = g_Vt + (size_t)g * 262144;
#pragma unroll
        for (int mf = 0; mf < 2; mf++) {
            const int r0 = tm * 128 + rb + mf * 16 + ty, r1 = r0 + 8;
#pragma unroll
            for (int nf = 0; nf < 8; nf++) {
                const int e0 = tn * 128 + nb + nf * 8 + tx * 2;
                const float b0 = __ldg(&bias[e0]), b1 = __ldg(&bias[e0 + 1]);
                dst[(size_t)e0 * 1024 + r0]       = __uint_as_float(f2tf(acc[mf][nf][0] + b0));
                dst[(size_t)(e0 + 1) * 1024 + r0] = __uint_as_float(f2tf(acc[mf][nf][1] + b1));
                dst[(size_t)e0 * 1024 + r1]       = __uint_as_float(f2tf(acc[mf][nf][2] + b0));
                dst[(size_t)(e0 + 1) * 1024 + r1] = __uint_as_float(f2tf(acc[mf][nf][3] + b1));
            }
        }
    }
}

// ============================================================
// Attention v3: per (qtile=128, g), 256 thr, 8 warps = 4 row-pairs x 2.
// Warp (pr, n): S = partial over d-half n for rows [pr*32,+32) x 32 keys;
// exchange partial S via smem (piggy-backed on pre-PV sync); both warps
// softmax identically; PV: warp n computes e-half n over all 32 keys with
// register-resident P.  Q resident (swizzled); K/V 2-slot cp.async ring.
// smem: Q 131072 | ring 2x32768 | exchange 32768 = 229376 B.
// ============================================================
#define ATT_SMEM 229376

__global__ void __launch_bounds__(256, 1)
attn_mma(float* __restrict__ out)
{
    extern __shared__ float smf[];
    const int qt = blockIdx.x, g = blockIdx.y;
    const int bb = g / 9, cc = (g / 3) % 3, hh = g % 3;
    const int q0 = qt * 128;
    const int tid = threadIdx.x, wid = tid >> 5, lane = tid & 31;
    const int ty = lane >> 2, tx = lane & 3;
    const int pr = wid >> 1, en = wid & 1;     // row-pair, e/d-half lane
    const int rb = pr * 32;                    // 32 q-rows per pair
    const size_t gbase = (size_t)g * 262144;
    const float* Qg = g_Q + gbase + (size_t)q0 * 256;
    const float* Kg = g_K + gbase;
    const float* Vg = g_Vt + gbase;
    const uint32_t sQ = smem_u32(smf);
    const uint32_t sR = sQ + 131072;           // 2 x 32768
    const uint32_t sX = sR + 65536;            // exchange: 8 x 4096

    const int lrow = lane & 15;
    const int kh   = lane >> 4;
    const uint32_t xr = (uint32_t)(lane & 7) << 4;   // XOR swizzle term

    // ---- stage Q once (swizzled): 128 rows x 64 float4 ----
#pragma unroll
    for (int it = 0; it < 32; it++) {
        int i = tid + it * 256;
        int r = i >> 6, c4 = i & 63;
        cpa16(sQ + r * 1024 + ((uint32_t)(c4 ^ (r & 7)) << 4),
              Qg + (size_t)r * 256 + c4 * 4);
    }
    CP_COMMIT;

    // loads idx 0..63: even -> K block idx/2, odd -> V block idx/2; slot idx&1
    auto stage = [&](int idx) {
        if (idx >= 64) return;
        const int kb_ = idx >> 1, slot = idx & 1;
        const uint32_t dB = sR + slot * 32768;
        if ((idx & 1) == 0) {       // K: 32 keys x 256 d
            const float* Kc = Kg + (size_t)(kb_ * 32) * 256;
#pragma unroll
            for (int it = 0; it < 8; it++) {
                int i = tid + it * 256;
                int r = i >> 6, c4 = i & 63;
                cpa16(dB + r * 1024 + ((uint32_t)(c4 ^ (r & 7)) << 4),
                      Kc + (size_t)r * 256 + c4 * 4);
            }
        } else {                    // V: 256 e x 32 s
            const float* Vc = Vg + kb_ * 32;
#pragma unroll
            for (int it = 0; it < 8; it++) {
                int i = tid + it * 256;
                int e = i >> 3, c4 = i & 7;
                cpa16(dB + e * 128 + ((uint32_t)(c4 ^ (e & 7)) << 4),
                      Vc + (size_t)e * 1024 + c4 * 4);
            }
        }
        CP_COMMIT;
    };

    float Oac[2][16][4];           // 32 rows (2 mf) x 128 e (16 nf)
#pragma unroll
    for (int mf = 0; mf < 2; mf++)
#pragma unroll
        for (int nf = 0; nf < 16; nf++)
#pragma unroll
            for (int k = 0; k < 4; k++) Oac[mf][nf][k] = 0.f;
    float lacA[2] = {0.f, 0.f}, lacB[2] = {0.f, 0.f};
    uint32_t pa[2][4][4];

    const uint32_t qA0 = sQ + (uint32_t)(rb + lrow) * 1024;
    const uint32_t qA1 = qA0 + 16 * 1024;
    const uint32_t xW = sX + (uint32_t)wid * 4096 + (uint32_t)lane * 16;
    const uint32_t xRd = sX + (uint32_t)(wid ^ 1) * 4096 + (uint32_t)lane * 16;

    stage(0);

#pragma unroll 1
    for (int kb = 0; kb < 32; kb++) {
        // ---- S partial = Q(d-half en) . K^T ----
        CP_WAIT(0);
        __syncthreads();
        stage(2 * kb + 1);         // V of this block -> other slot
        float Sac[2][4][4];
#pragma unroll
        for (int mf = 0; mf < 2; mf++)
#pragma unroll
            for (int nf = 0; nf < 4; nf++)
#pragma unroll
                for (int k = 0; k < 4; k++) Sac[mf][nf][k] = 0.f;
        {
            const uint32_t kA = sR + ((2 * kb) & 1) * 32768 + (uint32_t)lrow * 1024;
#pragma unroll
            for (int k = 0; k < 16; k++) {
                const int ks = en * 16 + k;
                uint32_t a0[4], a1[4], b0[4], b1[4];
                const uint32_t so = ((uint32_t)(ks * 2 + kh) << 4) ^ xr;
                ldsm4(a0, qA0 + so);
                ldsm4(a1, qA1 + so);
                ldsm4(b0, kA + so);
                ldsm4(b1, kA + 16384 + so);
                mma8(Sac[0][0], a0, b0[0], b0[2]);
                mma8(Sac[0][1], a0, b0[1], b0[3]);
                mma8(Sac[0][2], a0, b1[0], b1[2]);
                mma8(Sac[0][3], a0, b1[1], b1[3]);
                mma8(Sac[1][0], a1, b0[0], b0[2]);
                mma8(Sac[1][1], a1, b0[1], b0[3]);
                mma8(Sac[1][2], a1, b1[0], b1[2]);
                mma8(Sac[1][3], a1, b1[1], b1[3]);
            }
        }
        // write partial S for sibling
#pragma unroll
        for (int mf = 0; mf < 2; mf++)
#pragma unroll
            for (int nf = 0; nf < 4; nf++)
                *(float4*)(smf + ((xW + (uint32_t)(mf * 4 + nf) * 512) - sQ) / 4) =
                    make_float4(Sac[mf][nf][0], Sac[mf][nf][1], Sac[mf][nf][2], Sac[mf][nf][3]);

        // ---- sync: V staged AND partials visible ----
        CP_WAIT(0);
        __syncthreads();
        stage(2 * kb + 2);         // K of next block

        // add sibling partial, softmax, transpose to PV A-frags
        const int srcA = (lane & 28) | (tx >> 1);
        const int srcB = srcA + 2;
        const bool odd = (tx & 1);
#pragma unroll
        for (int mf = 0; mf < 2; mf++) {
#pragma unroll
            for (int nf = 0; nf < 4; nf++) {
                float4 sib = *(const float4*)(smf + ((xRd + (uint32_t)(mf * 4 + nf) * 512) - sQ) / 4);
                float e0 = ex2f(Sac[mf][nf][0] + sib.x);
                float e1 = ex2f(Sac[mf][nf][1] + sib.y);
                float e2 = ex2f(Sac[mf][nf][2] + sib.z);
                float e3 = ex2f(Sac[mf][nf][3] + sib.w);
                lacA[mf] += e0 + e1;
                lacB[mf] += e2 + e3;
                uint32_t s0 = f2tf(e0), s1 = f2tf(e1), s2 = f2tf(e2), s3 = f2tf(e3);
                uint32_t u0 = __shfl_sync(0xffffffffu, s0, srcA);
                uint32_t u1 = __shfl_sync(0xffffffffu, s1, srcA);
                uint32_t u2 = __shfl_sync(0xffffffffu, s2, srcA);
                uint32_t u3 = __shfl_sync(0xffffffffu, s3, srcA);
                uint32_t v0 = __shfl_sync(0xffffffffu, s0, srcB);
                uint32_t v1 = __shfl_sync(0xffffffffu, s1, srcB);
                uint32_t v2 = __shfl_sync(0xffffffffu, s2, srcB);
                uint32_t v3 = __shfl_sync(0xffffffffu, s3, srcB);
                pa[mf][nf][0] = odd ? u1 : u0;
                pa[mf][nf][1] = odd ? u3 : u2;
                pa[mf][nf][2] = odd ? v1 : v0;
                pa[mf][nf][3] = odd ? v3 : v2;
            }
        }

        // ---- O += P . Vt (e-half en, all 32 keys) ----
        {
            const uint32_t vA = sR + ((2 * kb + 1) & 1) * 32768
                              + (uint32_t)(en * 128 + lrow) * 128;
#pragma unroll
            for (int ks = 0; ks < 4; ks++) {
                const uint32_t so = ((uint32_t)(ks * 2 + kh) << 4) ^ xr;
#pragma unroll
                for (int p = 0; p < 8; p++) {
                    uint32_t vf[4];
                    ldsm4(vf, vA + p * 2048 + so);
                    mma8(Oac[0][2 * p],     pa[0][ks], vf[0], vf[2]);
                    mma8(Oac[0][2 * p + 1], pa[0][ks], vf[1], vf[3]);
                    mma8(Oac[1][2 * p],     pa[1][ks], vf[0], vf[2]);
                    mma8(Oac[1][2 * p + 1], pa[1][ks], vf[1], vf[3]);
                }
            }
        }
    }

    // ---- epilogue: warp-local row sums, O/l, store ----
#pragma unroll
    for (int mf = 0; mf < 2; mf++) {
        lacA[mf] += __shfl_xor_sync(0xffffffffu, lacA[mf], 1);
        lacA[mf] += __shfl_xor_sync(0xffffffffu, lacA[mf], 2);
        lacB[mf] += __shfl_xor_sync(0xffffffffu, lacB[mf], 1);
        lacB[mf] += __shfl_xor_sync(0xffffffffu, lacB[mf], 2);
    }
#pragma unroll
    for (int mf = 0; mf < 2; mf++) {
        const float inv0 = 1.f / lacA[mf];
        const float inv1 = 1.f / lacB[mf];
        const int r0 = q0 + rb + mf * 16 + ty;
        float* o0 = out + ((size_t)(bb * 1024 + r0)) * 2304 + cc * 768 + hh * 256 + en * 128;
        float* o1 = o0 + (size_t)8 * 2304;
#pragma unroll
        for (int nf = 0; nf < 16; nf++) {
            const int ccol = nf * 8 + tx * 2;
            *(float2*)&o0[ccol] = make_float2(Oac[mf][nf][0] * inv0, Oac[mf][nf][1] * inv0);
            *(float2*)&o1[ccol] = make_float2(Oac[mf][nf][2] * inv1, Oac[mf][nf][3] * inv1);
        }
    }
}

// ============================================================
extern "C" void kernel_launch(void* const* d_in, const int* in_sizes, int n_in,
                              void* d_out, int out_size)
{
    const float* x  = (const float*)d_in[0];
    const float* Wq = (const float*)d_in[1];
    const float* bq = (const float*)d_in[2];
    const float* Wk = (const float*)d_in[3];
    const float* bk = (const float*)d_in[4];
    const float* Wv = (const float*)d_in[5];
    const float* bv = (const float*)d_in[6];
    float* out = (float*)d_out;

    cudaFuncSetAttribute(qkv_mma,  cudaFuncAttributeMaxDynamicSharedMemorySize, QKV_SMEM);
    cudaFuncSetAttribute(attn_mma, cudaFuncAttributeMaxDynamicSharedMemorySize, ATT_SMEM);

    qkv_mma<<<dim3(16, 72, 3), 256, QKV_SMEM>>>(x, Wq, bq, Wk, bk, Wv, bv);
    attn_mma<<<dim3(8, 72), 256, ATT_SMEM>>>(out);
}

// round 15
// speedup vs baseline: 1.1741x; 1.1741x over previous
#include <cuda_runtime.h>
#include <cuda_fp16.h>
#include <cstdint>

#define SQ_ 0.09016844005556022f   // (1/16)*log2(e)

static __device__ float g_Q [18874368];      // [g][s][d] scaled by SQ_, tf32-rounded
static __device__ float g_K [18874368];      // [g][s][d] tf32-rounded
static __device__ __half g_Vh[18874368];     // [g][e][s] fp16 (transposed V)

__device__ __forceinline__ uint32_t smem_u32(const void* p) {
    uint32_t a;
    asm("{ .reg .u64 t; cvta.to.shared.u64 t, %1; cvt.u32.u64 %0, t; }" : "=r"(a) : "l"(p));
    return a;
}
__device__ __forceinline__ void cpa16(uint32_t d, const void* s) {
    asm volatile("cp.async.cg.shared.global [%0], [%1], 16;\n" :: "r"(d), "l"(s));
}
#define CP_COMMIT  asm volatile("cp.async.commit_group;\n" ::: "memory")
#define CP_WAIT(n) asm volatile("cp.async.wait_group %0;\n" :: "n"(n) : "memory")

__device__ __forceinline__ uint32_t f2tf(float x) {
    uint32_t u; asm("cvt.rna.tf32.f32 %0, %1;" : "=r"(u) : "f"(x)); return u;
}
__device__ __forceinline__ float ex2f(float x) {
    float y; asm("ex2.approx.ftz.f32 %0, %1;" : "=f"(y) : "f"(x)); return y;
}
__device__ __forceinline__ uint32_t packh2(float hi, float lo) {   // upper=hi, lower=lo
    uint32_t r; asm("cvt.rn.f16x2.f32 %0, %1, %2;" : "=r"(r) : "f"(hi), "f"(lo)); return r;
}
__device__ __forceinline__ void mma8(float* c, const uint32_t* a, const uint32_t b0, const uint32_t b1) {
    asm volatile("mma.sync.aligned.m16n8k8.row.col.f32.tf32.tf32.f32 "
                 "{%0,%1,%2,%3}, {%4,%5,%6,%7}, {%8,%9}, {%0,%1,%2,%3};\n"
                 : "+f"(c[0]), "+f"(c[1]), "+f"(c[2]), "+f"(c[3])
                 : "r"(a[0]), "r"(a[1]), "r"(a[2]), "r"(a[3]), "r"(b0), "r"(b1));
}
__device__ __forceinline__ void mma16h(float* c, const uint32_t* a, const uint32_t b0, const uint32_t b1) {
    asm volatile("mma.sync.aligned.m16n8k16.row.col.f32.f16.f16.f32 "
                 "{%0,%1,%2,%3}, {%4,%5,%6,%7}, {%8,%9}, {%0,%1,%2,%3};\n"
                 : "+f"(c[0]), "+f"(c[1]), "+f"(c[2]), "+f"(c[3])
                 : "r"(a[0]), "r"(a[1]), "r"(a[2]), "r"(a[3]), "r"(b0), "r"(b1));
}
__device__ __forceinline__ void ldsm4(uint32_t* r, uint32_t addr) {
    asm volatile("ldmatrix.sync.aligned.m8n8.x4.shared.b16 {%0,%1,%2,%3}, [%4];"
                 : "=r"(r[0]), "=r"(r[1]), "=r"(r[2]), "=r"(r[3]) : "r"(addr));
}

// ============================================================
// QKV (r7 structure, proven): CTA 128x128, 256 thr, 3-stage cp.async ring.
// Q/K tf32-rounded fp32 (Q pre-scaled); V transposed + fp16.
// ============================================================
#define QKV_SMEM 110592

__global__ void __launch_bounds__(256, 2)
qkv_mma(const float* __restrict__ x,
        const float* __restrict__ Wq, const float* __restrict__ bq,
        const float* __restrict__ Wk, const float* __restrict__ bk,
        const float* __restrict__ Wv, const float* __restrict__ bv)
{
    extern __shared__ float smf[];
    float* As = smf;            // 3 x 4608
    float* Bs = smf + 13824;    // 3 x 4608

    const int tile = blockIdx.x, g = blockIdx.y, z = blockIdx.z;
    const int tm = tile >> 1, tn = tile & 1;
    const int hh = g % 3;
    const int tid = threadIdx.x, wid = tid >> 5, lane = tid & 31;
    const int ty = lane >> 2, tx = lane & 3;
    const int warpM = wid >> 1, warpN = wid & 1;
    const int rb = warpM * 32, nb = warpN * 64;

    const float* W; const float* bias;
    if (z == 0)      { W = Wq; bias = bq; }
    else if (z == 1) { W = Wk; bias = bk; }
    else             { W = Wv; bias = bv; }
    W += hh * 65536;  bias += hh * 256;

    const float* X  = x + ((size_t)((g / 3) * 1024 + tm * 128)) * 768 + hh * 256;
    const float* Wp = W + tn * 128 * 256;
    const uint32_t sA = smem_u32(As), sB = smem_u32(Bs);

    auto stage = [&](int dc_) {
        if (dc_ >= 8) return;
        const int bf_ = dc_ % 3;
        uint32_t dA = sA + bf_ * 18432, dB = sB + bf_ * 18432;
#pragma unroll
        for (int it = 0; it < 4; it++) {
            int i = tid + it * 256, r = i >> 3, c4 = i & 7;
            cpa16(dA + r * 144 + c4 * 16, X  + (size_t)r * 768 + dc_ * 32 + c4 * 4);
            cpa16(dB + r * 144 + c4 * 16, Wp + r * 256 + dc_ * 32 + c4 * 4);
        }
        CP_COMMIT;
    };

    float acc[2][8][4];
#pragma unroll
    for (int mf = 0; mf < 2; mf++)
#pragma unroll
        for (int nf = 0; nf < 8; nf++)
#pragma unroll
            for (int k = 0; k < 4; k++) acc[mf][nf][k] = 0.f;

    stage(0); stage(1);
#pragma unroll 1
    for (int dc = 0; dc < 8; dc++) {
        const int bf = dc % 3;
        CP_WAIT(1);
        __syncthreads();
        stage(dc + 2);
        const float* Aq = As + bf * 4608;
        const float* Bk = Bs + bf * 4608;
#pragma unroll
        for (int ks = 0; ks < 4; ks++) {
            uint32_t af[2][4], bfr[8][2];
            const int kc = ks * 8 + tx;
#pragma unroll
            for (int mf = 0; mf < 2; mf++) {
                const float* ap = Aq + (rb + mf * 16 + ty) * 36 + kc;
                af[mf][0] = f2tf(ap[0]);
                af[mf][1] = f2tf(ap[8 * 36]);
                af[mf][2] = f2tf(ap[4]);
                af[mf][3] = f2tf(ap[8 * 36 + 4]);
            }
#pragma unroll
            for (int nf = 0; nf < 8; nf++) {
                const float* bp = Bk + (nb + nf * 8 + ty) * 36 + kc;
                bfr[nf][0] = f2tf(bp[0]);
                bfr[nf][1] = f2tf(bp[4]);
            }
#pragma unroll
            for (int mf = 0; mf < 2; mf++)
#pragma unroll
                for (int nf = 0; nf < 8; nf++)
                    mma8(acc[mf][nf], af[mf], bfr[nf][0], bfr[nf][1]);
        }
    }

    if (z < 2) {
        float* dst = (z == 0 ? g_Q : g_K) + (size_t)g * 262144;
        const float osc = (z == 0) ? SQ_ : 1.0f;
#pragma unroll
        for (int mf = 0; mf < 2; mf++) {
            const int r0 = tm * 128 + rb + mf * 16 + ty, r1 = r0 + 8;
#pragma unroll
            for (int nf = 0; nf < 8; nf++) {
                const int ccol = tn * 128 + nb + nf * 8 + tx * 2;
                const float b0 = __ldg(&bias[ccol]), b1 = __ldg(&bias[ccol + 1]);
                *(float2*)&dst[(size_t)r0 * 256 + ccol] = make_float2(
                    __uint_as_float(f2tf((acc[mf][nf][0] + b0) * osc)),
                    __uint_as_float(f2tf((acc[mf][nf][1] + b1) * osc)));
                *(float2*)&dst[(size_t)r1 * 256 + ccol] = make_float2(
                    __uint_as_float(f2tf((acc[mf][nf][2] + b0) * osc)),
                    __uint_as_float(f2tf((acc[mf][nf][3] + b1) * osc)));
            }
        }
    } else {
        __half* dst = g_Vh + (size_t)g * 262144;
#pragma unroll
        for (int mf = 0; mf < 2; mf++) {
            const int r0 = tm * 128 + rb + mf * 16 + ty, r1 = r0 + 8;
#pragma unroll
            for (int nf = 0; nf < 8; nf++) {
                const int e0 = tn * 128 + nb + nf * 8 + tx * 2;
                const float b0 = __ldg(&bias[e0]), b1 = __ldg(&bias[e0 + 1]);
                dst[(size_t)e0 * 1024 + r0]       = __float2half(acc[mf][nf][0] + b0);
                dst[(size_t)(e0 + 1) * 1024 + r0] = __float2half(acc[mf][nf][1] + b1);
                dst[(size_t)e0 * 1024 + r1]       = __float2half(acc[mf][nf][2] + b0);
                dst[(size_t)(e0 + 1) * 1024 + r1] = __float2half(acc[mf][nf][3] + b1);
            }
        }
    }
}

// ============================================================
// Attention v4h (r11 structure + fp16 PV): per (qtile=128, g), 256 thr, 8 warps.
// Warp = 16 q-rows x 32-key block.  S in tf32 (k8 mma); softmax packs P
// directly into fp16 A-frags (no shuffle transpose); PV via m16n8k16 fp16.
// Q resident (swizzled, 131072 B); K ring 2x32768 @+131072; V(fp16) ring
// 2x16384 @+196608.  Total smem = 229376 B.
// ============================================================
#define ATT_SMEM 229376

__global__ void __launch_bounds__(256, 1)
attn_mma(float* __restrict__ out)
{
    extern __shared__ float smf[];
    const int qt = blockIdx.x, g = blockIdx.y;
    const int bb = g / 9, cc = (g / 3) % 3, hh = g % 3;
    const int q0 = qt * 128;
    const int tid = threadIdx.x, wid = tid >> 5, lane = tid & 31;
    const int ty = lane >> 2, tx = lane & 3;
    const int rb = wid * 16;                      // 16 q-rows per warp
    const size_t gbase = (size_t)g * 262144;
    const float* Qg = g_Q + gbase + (size_t)q0 * 256;
    const float* Kg = g_K + gbase;
    const __half* Vh = g_Vh + gbase;
    const uint32_t sQ = smem_u32(smf);
    const uint32_t sK = sQ + 131072;             // 2 x 32768
    const uint32_t sV = sQ + 196608;             // 2 x 16384

    const int lrow = lane & 15;
    const int kh   = lane >> 4;
    const uint32_t xr = (uint32_t)(lane & 7) << 4;         // XOR swizzle (K/Q)
    const uint32_t qA = sQ + (uint32_t)(rb + lrow) * 1024; // Q row base

    // V ldsm per-lane addressing: er = e-row within 16-row block; sgbit = k-seg bit
    const int er = (lane & 7) | ((lane >> 4) << 3);
    const int sgbit = (lane >> 3) & 1;
    const int vq = (er >> 1) & 3;                          // V swizzle term
    const uint32_t vrow = (uint32_t)er * 64;

    // ---- stage Q once (swizzled): 128 rows x 64 float4 ----
#pragma unroll
    for (int it = 0; it < 32; it++) {
        int i = tid + it * 256;
        int r = i >> 6, c4 = i & 63;
        cpa16(sQ + r * 1024 + ((uint32_t)(c4 ^ (r & 7)) << 4),
              Qg + (size_t)r * 256 + c4 * 4);
    }
    CP_COMMIT;

    // loads idx 0..63: even -> K block idx/2 (slot (idx/2)&1),
    //                  odd  -> V block idx/2 (slot (idx/2)&1)
    auto stage = [&](int idx) {
        if (idx >= 64) return;
        const int kb_ = idx >> 1, slot = kb_ & 1;
        if ((idx & 1) == 0) {       // K: 32 keys x 256 d fp32
            const float* Kc = Kg + (size_t)(kb_ * 32) * 256;
            const uint32_t dB = sK + slot * 32768;
#pragma unroll
            for (int it = 0; it < 8; it++) {
                int i = tid + it * 256;
                int r = i >> 6, c4 = i & 63;
                cpa16(dB + r * 1024 + ((uint32_t)(c4 ^ (r & 7)) << 4),
                      Kc + (size_t)r * 256 + c4 * 4);
            }
        } else {                    // V: 256 e x 32 s fp16 = 16384 B
            const __half* Vc = Vh + kb_ * 32;
            const uint32_t dB = sV + slot * 16384;
#pragma unroll
            for (int it = 0; it < 4; it++) {
                int i = tid + it * 256;
                int e = i >> 2, sg = i & 3;
                cpa16(dB + e * 64 + ((uint32_t)(sg ^ ((e >> 1) & 3)) << 4),
                      Vc + (size_t)e * 1024 + sg * 8);
            }
        }
        CP_COMMIT;
    };

    float Oac[32][4];
#pragma unroll
    for (int j = 0; j < 32; j++)
#pragma unroll
        for (int k = 0; k < 4; k++) Oac[j][k] = 0.f;
    float lac0 = 0.f, lac1 = 0.f;
    uint32_t pa[2][4];

    stage(0); stage(1);

#pragma unroll 1
    for (int kb = 0; kb < 32; kb++) {
        // ---- S = Q . K^T for this 32-key block (tf32) ----
        CP_WAIT(1);
        __syncthreads();
        stage(2 * kb + 2);
        {
            const uint32_t kA = sK + (uint32_t)(kb & 1) * 32768 + (uint32_t)lrow * 1024;
            float Sac[4][4];
#pragma unroll
            for (int nf = 0; nf < 4; nf++)
#pragma unroll
                for (int k = 0; k < 4; k++) Sac[nf][k] = 0.f;
#pragma unroll
            for (int ks = 0; ks < 32; ks++) {
                uint32_t af[4], b0[4], b1[4];
                const uint32_t so = ((uint32_t)(ks * 2 + kh) << 4) ^ xr;
                ldsm4(af, qA + so);
                ldsm4(b0, kA + so);
                ldsm4(b1, kA + 16384 + so);
                mma8(Sac[0], af, b0[0], b0[2]);
                mma8(Sac[1], af, b0[1], b0[3]);
                mma8(Sac[2], af, b1[0], b1[2]);
                mma8(Sac[3], af, b1[1], b1[3]);
            }

            // ---- softmax (ref max 0) + direct fp16 A-frag pack ----
#pragma unroll
            for (int nf = 0; nf < 4; nf++) {
                float e0 = ex2f(Sac[nf][0]);
                float e1 = ex2f(Sac[nf][1]);
                float e2 = ex2f(Sac[nf][2]);
                float e3 = ex2f(Sac[nf][3]);
                lac0 += e0 + e1;
                lac1 += e2 + e3;
                const int kk = nf >> 1, hi = (nf & 1) * 2;
                pa[kk][hi + 0] = packh2(e1, e0);   // (row g,   k 2t..2t+1)
                pa[kk][hi + 1] = packh2(e3, e2);   // (row g+8, k 2t..2t+1)
            }
        }

        // ---- O += P . V (fp16, m16n8k16) ----
        CP_WAIT(1);
        __syncthreads();
        stage(2 * kb + 3);
        {
            const uint32_t vA = sV + (uint32_t)(kb & 1) * 16384 + vrow;
#pragma unroll
            for (int kk = 0; kk < 2; kk++) {
                const uint32_t voff = ((uint32_t)((2 * kk + sgbit) ^ vq)) << 4;
#pragma unroll
                for (int p = 0; p < 16; p++) {
                    uint32_t vf[4];
                    ldsm4(vf, vA + p * 1024 + voff);
                    mma16h(Oac[2 * p],     pa[kk], vf[0], vf[1]);
                    mma16h(Oac[2 * p + 1], pa[kk], vf[2], vf[3]);
                }
            }
        }
    }

    // ---- epilogue: warp-local row sums, O/l, store ----
    lac0 += __shfl_xor_sync(0xffffffffu, lac0, 1);
    lac0 += __shfl_xor_sync(0xffffffffu, lac0, 2);
    lac1 += __shfl_xor_sync(0xffffffffu, lac1, 1);
    lac1 += __shfl_xor_sync(0xffffffffu, lac1, 2);
    const float inv0 = 1.f / lac0;
    const float inv1 = 1.f / lac1;
    const int r0 = q0 + rb + ty;
    float* o0 = out + ((size_t)(bb * 1024 + r0)) * 2304 + cc * 768 + hh * 256;
    float* o1 = o0 + (size_t)8 * 2304;
#pragma unroll
    for (int j = 0; j < 32; j++) {
        const int ccol = j * 8 + tx * 2;
        *(float2*)&o0[ccol] = make_float2(Oac[j][0] * inv0, Oac[j][1] * inv0);
        *(float2*)&o1[ccol] = make_float2(Oac[j][2] * inv1, Oac[j][3] * inv1);
    }
}

// ============================================================
extern "C" void kernel_launch(void* const* d_in, const int* in_sizes, int n_in,
                              void* d_out, int out_size)
{
    const float* x  = (const float*)d_in[0];
    const float* Wq = (const float*)d_in[1];
    const float* bq = (const float*)d_in[2];
    const float* Wk = (const float*)d_in[3];
    const float* bk = (const float*)d_in[4];
    const float* Wv = (const float*)d_in[5];
    const float* bv = (const float*)d_in[6];
    float* out = (float*)d_out;

    cudaFuncSetAttribute(qkv_mma,  cudaFuncAttributeMaxDynamicSharedMemorySize, QKV_SMEM);
    cudaFuncSetAttribute(attn_mma, cudaFuncAttributeMaxDynamicSharedMemorySize, ATT_SMEM);

    qkv_mma<<<dim3(16, 72, 3), 256, QKV_SMEM>>>(x, Wq, bq, Wk, bk, Wv, bv);
    attn_mma<<<dim3(8, 72), 256, ATT_SMEM>>>(out);
}

// round 17
// speedup vs baseline: 1.5354x; 1.3077x over previous
#include <cuda_runtime.h>
#include <cuda_fp16.h>
#include <cstdint>

#define SQ_ 0.09016844005556022f   // (1/16)*log2(e)

static __device__ __half g_Qh[18874368];   // [g][s][d] fp16, pre-scaled by SQ_
static __device__ __half g_Kh[18874368];   // [g][s][d] fp16
static __device__ __half g_Vh[18874368];   // [g][e][s] fp16 (transposed V)

__device__ __forceinline__ uint32_t smem_u32(const void* p) {
    uint32_t a;
    asm("{ .reg .u64 t; cvta.to.shared.u64 t, %1; cvt.u32.u64 %0, t; }" : "=r"(a) : "l"(p));
    return a;
}
__device__ __forceinline__ void cpa16(uint32_t d, const void* s) {
    asm volatile("cp.async.cg.shared.global [%0], [%1], 16;\n" :: "r"(d), "l"(s));
}
#define CP_COMMIT  asm volatile("cp.async.commit_group;\n" ::: "memory")
#define CP_WAIT(n) asm volatile("cp.async.wait_group %0;\n" :: "n"(n) : "memory")

__device__ __forceinline__ uint32_t f2tf(float x) {
    uint32_t u; asm("cvt.rna.tf32.f32 %0, %1;" : "=r"(u) : "f"(x)); return u;
}
__device__ __forceinline__ float ex2f(float x) {
    float y; asm("ex2.approx.ftz.f32 %0, %1;" : "=f"(y) : "f"(x)); return y;
}
__device__ __forceinline__ uint32_t packh2(float hi, float lo) {   // upper=hi, lower=lo
    uint32_t r; asm("cvt.rn.f16x2.f32 %0, %1, %2;" : "=r"(r) : "f"(hi), "f"(lo)); return r;
}
__device__ __forceinline__ void mma8(float* c, const uint32_t* a, const uint32_t b0, const uint32_t b1) {
    asm volatile("mma.sync.aligned.m16n8k8.row.col.f32.tf32.tf32.f32 "
                 "{%0,%1,%2,%3}, {%4,%5,%6,%7}, {%8,%9}, {%0,%1,%2,%3};\n"
                 : "+f"(c[0]), "+f"(c[1]), "+f"(c[2]), "+f"(c[3])
                 : "r"(a[0]), "r"(a[1]), "r"(a[2]), "r"(a[3]), "r"(b0), "r"(b1));
}
__device__ __forceinline__ void mma16h(float* c, const uint32_t* a, const uint32_t b0, const uint32_t b1) {
    asm volatile("mma.sync.aligned.m16n8k16.row.col.f32.f16.f16.f32 "
                 "{%0,%1,%2,%3}, {%4,%5,%6,%7}, {%8,%9}, {%0,%1,%2,%3};\n"
                 : "+f"(c[0]), "+f"(c[1]), "+f"(c[2]), "+f"(c[3])
                 : "r"(a[0]), "r"(a[1]), "r"(a[2]), "r"(a[3]), "r"(b0), "r"(b1));
}
__device__ __forceinline__ void ldsm4(uint32_t* r, uint32_t addr) {
    asm volatile("ldmatrix.sync.aligned.m8n8.x4.shared.b16 {%0,%1,%2,%3}, [%4];"
                 : "=r"(r[0]), "=r"(r[1]), "=r"(r[2]), "=r"(r[3]) : "r"(addr));
}

// ============================================================
// QKV: CTA 128x128, 256 thr, 3-stage cp.async ring (tf32 compute).
// Outputs fp16: Q pre-scaled by SQ_; K direct; V transposed via smem
// (coalesced global writes).  stage() ALWAYS commits.
// ============================================================
#define QKV_SMEM 110592

__global__ void __launch_bounds__(256, 2)
qkv_mma(const float* __restrict__ x,
        const float* __restrict__ Wq, const float* __restrict__ bq,
        const float* __restrict__ Wk, const float* __restrict__ bk,
        const float* __restrict__ Wv, const float* __restrict__ bv)
{
    extern __shared__ float smf[];
    float* As = smf;            // 3 x 4608
    float* Bs = smf + 13824;    // 3 x 4608

    const int tile = blockIdx.x, g = blockIdx.y, z = blockIdx.z;
    const int tm = tile >> 1, tn = tile & 1;
    const int hh = g % 3;
    const int tid = threadIdx.x, wid = tid >> 5, lane = tid & 31;
    const int ty = lane >> 2, tx = lane & 3;
    const int warpM = wid >> 1, warpN = wid & 1;
    const int rb = warpM * 32, nb = warpN * 64;

    const float* W; const float* bias;
    if (z == 0)      { W = Wq; bias = bq; }
    else if (z == 1) { W = Wk; bias = bk; }
    else             { W = Wv; bias = bv; }
    W += hh * 65536;  bias += hh * 256;

    const float* X  = x + ((size_t)((g / 3) * 1024 + tm * 128)) * 768 + hh * 256;
    const float* Wp = W + tn * 128 * 256;
    const uint32_t sA = smem_u32(As), sB = smem_u32(Bs);

    auto stage = [&](int dc_) {
        if (dc_ < 8) {
            const int bf_ = dc_ % 3;
            uint32_t dA = sA + bf_ * 18432, dB = sB + bf_ * 18432;
#pragma unroll
            for (int it = 0; it < 4; it++) {
                int i = tid + it * 256, r = i >> 3, c4 = i & 7;
                cpa16(dA + r * 144 + c4 * 16, X  + (size_t)r * 768 + dc_ * 32 + c4 * 4);
                cpa16(dB + r * 144 + c4 * 16, Wp + r * 256 + dc_ * 32 + c4 * 4);
            }
        }
        CP_COMMIT;
    };

    float acc[2][8][4];
#pragma unroll
    for (int mf = 0; mf < 2; mf++)
#pragma unroll
        for (int nf = 0; nf < 8; nf++)
#pragma unroll
            for (int k = 0; k < 4; k++) acc[mf][nf][k] = 0.f;

    stage(0); stage(1);
#pragma unroll 1
    for (int dc = 0; dc < 8; dc++) {
        const int bf = dc % 3;
        CP_WAIT(1);
        __syncthreads();
        stage(dc + 2);
        const float* Aq = As + bf * 4608;
        const float* Bk = Bs + bf * 4608;
#pragma unroll
        for (int ks = 0; ks < 4; ks++) {
            uint32_t af[2][4], bfr[8][2];
            const int kc = ks * 8 + tx;
#pragma unroll
            for (int mf = 0; mf < 2; mf++) {
                const float* ap = Aq + (rb + mf * 16 + ty) * 36 + kc;
                af[mf][0] = f2tf(ap[0]);
                af[mf][1] = f2tf(ap[8 * 36]);
                af[mf][2] = f2tf(ap[4]);
                af[mf][3] = f2tf(ap[8 * 36 + 4]);
            }
#pragma unroll
            for (int nf = 0; nf < 8; nf++) {
                const float* bp = Bk + (nb + nf * 8 + ty) * 36 + kc;
                bfr[nf][0] = f2tf(bp[0]);
                bfr[nf][1] = f2tf(bp[4]);
            }
#pragma unroll
            for (int mf = 0; mf < 2; mf++)
#pragma unroll
                for (int nf = 0; nf < 8; nf++)
                    mma8(acc[mf][nf], af[mf], bfr[nf][0], bfr[nf][1]);
        }
    }

    if (z < 2) {
        __half* dst = (z == 0 ? g_Qh : g_Kh) + (size_t)g * 262144;
        const float osc = (z == 0) ? SQ_ : 1.0f;
#pragma unroll
        for (int mf = 0; mf < 2; mf++) {
            const int r0 = tm * 128 + rb + mf * 16 + ty, r1 = r0 + 8;
#pragma unroll
            for (int nf = 0; nf < 8; nf++) {
                const int ccol = tn * 128 + nb + nf * 8 + tx * 2;
                const float b0 = __ldg(&bias[ccol]), b1 = __ldg(&bias[ccol + 1]);
                *(__half2*)&dst[(size_t)r0 * 256 + ccol] =
                    __floats2half2_rn((acc[mf][nf][0] + b0) * osc, (acc[mf][nf][1] + b1) * osc);
                *(__half2*)&dst[(size_t)r1 * 256 + ccol] =
                    __floats2half2_rn((acc[mf][nf][2] + b0) * osc, (acc[mf][nf][3] + b1) * osc);
            }
        }
    } else {
        // transpose through smem, then coalesced 16B global writes
        __syncthreads();
        __half* Vs = (__half*)smf;          // 128 e-rows x 136 (pad) halfs = 34816 B
#pragma unroll
        for (int mf = 0; mf < 2; mf++) {
            const int rL0 = rb + mf * 16 + ty, rL1 = rL0 + 8;
#pragma unroll
            for (int nf = 0; nf < 8; nf++) {
                const int eL = nb + nf * 8 + tx * 2;
                const float b0 = __ldg(&bias[tn * 128 + eL]), b1 = __ldg(&bias[tn * 128 + eL + 1]);
                Vs[eL * 136 + rL0]       = __float2half(acc[mf][nf][0] + b0);
                Vs[(eL + 1) * 136 + rL0] = __float2half(acc[mf][nf][1] + b1);
                Vs[eL * 136 + rL1]       = __float2half(acc[mf][nf][2] + b0);
                Vs[(eL + 1) * 136 + rL1] = __float2half(acc[mf][nf][3] + b1);
            }
        }
        __syncthreads();
        // 128 e-rows x 128 s halfs = 128 x 16 uint4 chunks (e = i>>4, c = i&15)
        __half* dst = g_Vh + (size_t)g * 262144 + (size_t)(tn * 128) * 1024 + tm * 128;
#pragma unroll
        for (int it = 0; it < 8; it++) {
            int i = tid + it * 256;
            int e = i >> 4, c = i & 15;
            uint4 v = *(const uint4*)(Vs + e * 136 + c * 8);
            *(uint4*)(dst + (size_t)e * 1024 + c * 8) = v;
        }
    }
}

// ============================================================
// Attention v5 (all-fp16 operands): per (qtile=128, g), 256 thr, 8 warps.
// Warp = 16 q-rows x 32-key block.  S via m16n8k16 fp16 (fp32 accum);
// softmax packs P into fp16 A-frags; PV via m16n8k16 fp16.
// Q resident fp16 (65536 B); K ring 2x16384 @+65536; V ring 2x16384 @+98304.
// Total smem = 131072 B.  All ldsm addressing seg^(row&7) swizzled.
// ============================================================
#define ATT_SMEM 131072

__global__ void __launch_bounds__(256, 1)
attn_mma(float* __restrict__ out)
{
    extern __shared__ float smf[];
    const int qt = blockIdx.x, g = blockIdx.y;
    const int bb = g / 9, cc = (g / 3) % 3, hh = g % 3;
    const int q0 = qt * 128;
    const int tid = threadIdx.x, wid = tid >> 5, lane = tid & 31;
    const int ty = lane >> 2, tx = lane & 3;
    const int rb = wid * 16;                      // 16 q-rows per warp
    const size_t gbase = (size_t)g * 262144;
    const __half* Qg = g_Qh + gbase + (size_t)q0 * 256;
    const __half* Kg = g_Kh + gbase;
    const __half* Vh = g_Vh + gbase;
    const uint32_t sQ = smem_u32(smf);
    const uint32_t sK = sQ + 65536;              // 2 x 16384
    const uint32_t sV = sQ + 98304;              // 2 x 16384

    const int lrow = lane & 15;
    const int kh   = lane >> 4;
    const uint32_t qA = sQ + (uint32_t)(rb + lrow) * 512;   // Q row base (512 B rows)

    // K/V B-frag lane addressing (r15-proven pattern)
    const int kn = (lane & 7) | ((lane >> 4) << 3);         // b-rows 0..15
    const int sgbit = (lane >> 3) & 1;                      // k-seg parity
    const int vq = (kn >> 1) & 3;                           // V swizzle term
    const uint32_t vrow = (uint32_t)kn * 64;

    // ---- stage Q once (swizzled): 128 rows x 32 16B-segs ----
#pragma unroll
    for (int it = 0; it < 16; it++) {
        int i = tid + it * 256;
        int r = i >> 5, sg = i & 31;
        cpa16(sQ + r * 512 + ((uint32_t)(sg ^ (r & 7)) << 4),
              Qg + (size_t)r * 256 + sg * 8);
    }
    CP_COMMIT;

    // loads idx 0..63: even -> K block idx/2, odd -> V block idx/2; slot (idx/2)&1
    // ALWAYS commits (empty group when idx >= 64).
    auto stage = [&](int idx) {
        if (idx < 64) {
            const int kb_ = idx >> 1, slot = kb_ & 1;
            if ((idx & 1) == 0) {       // K: 32 keys x 256 d fp16 = 16384 B
                const __half* Kc = Kg + (size_t)(kb_ * 32) * 256;
                const uint32_t dB = sK + slot * 16384;
#pragma unroll
                for (int it = 0; it < 4; it++) {
                    int i = tid + it * 256;
                    int r = i >> 5, sg = i & 31;
                    cpa16(dB + r * 512 + ((uint32_t)(sg ^ (r & 7)) << 4),
                          Kc + (size_t)r * 256 + sg * 8);
                }
            } else {                    // V: 256 e x 32 s fp16 = 16384 B
                const __half* Vc = Vh + kb_ * 32;
                const uint32_t dB = sV + slot * 16384;
#pragma unroll
                for (int it = 0; it < 4; it++) {
                    int i = tid + it * 256;
                    int e = i >> 2, sg = i & 3;
                    cpa16(dB + e * 64 + ((uint32_t)(sg ^ ((e >> 1) & 3)) << 4),
                          Vc + (size_t)e * 1024 + sg * 8);
                }
            }
        }
        CP_COMMIT;
    };

    float Oac[32][4];
#pragma unroll
    for (int j = 0; j < 32; j++)
#pragma unroll
        for (int k = 0; k < 4; k++) Oac[j][k] = 0.f;
    float lac0 = 0.f, lac1 = 0.f;
    uint32_t pa[2][4];

    stage(0); stage(1);

#pragma unroll 1
    for (int kb = 0; kb < 32; kb++) {
        // ---- S = Q . K^T for this 32-key block (fp16, fp32 accum) ----
        CP_WAIT(1);
        __syncthreads();
        stage(2 * kb + 2);
        {
            const uint32_t kA = sK + (uint32_t)(kb & 1) * 16384;
            const uint32_t kR0 = kA + (uint32_t)kn * 512;
            const uint32_t kR1 = kR0 + 16 * 512;
            float Sac[4][4];
#pragma unroll
            for (int nf = 0; nf < 4; nf++)
#pragma unroll
                for (int k = 0; k < 4; k++) Sac[nf][k] = 0.f;
#pragma unroll
            for (int ks = 0; ks < 16; ks++) {
                uint32_t af[4], bf0[4], bf1[4];
                const uint32_t qs = ((uint32_t)((2 * ks + kh) ^ (lrow & 7))) << 4;
                const uint32_t ksw = ((uint32_t)((2 * ks + sgbit) ^ (kn & 7))) << 4;
                ldsm4(af, qA + qs);
                ldsm4(bf0, kR0 + ksw);
                ldsm4(bf1, kR1 + ksw);
                mma16h(Sac[0], af, bf0[0], bf0[1]);   // keys 0-7
                mma16h(Sac[1], af, bf0[2], bf0[3]);   // keys 8-15
                mma16h(Sac[2], af, bf1[0], bf1[1]);   // keys 16-23
                mma16h(Sac[3], af, bf1[2], bf1[3]);   // keys 24-31
            }

            // ---- softmax (ref max 0) + direct fp16 A-frag pack ----
#pragma unroll
            for (int nf = 0; nf < 4; nf++) {
                float e0 = ex2f(Sac[nf][0]);
                float e1 = ex2f(Sac[nf][1]);
                float e2 = ex2f(Sac[nf][2]);
                float e3 = ex2f(Sac[nf][3]);
                lac0 += e0 + e1;
                lac1 += e2 + e3;
                const int kk = nf >> 1, hi = (nf & 1) * 2;
                pa[kk][hi + 0] = packh2(e1, e0);   // (row g,   k 2t..2t+1)
                pa[kk][hi + 1] = packh2(e3, e2);   // (row g+8, k 2t..2t+1)
            }
        }

        // ---- O += P . V (fp16, m16n8k16) ----
        CP_WAIT(1);
        __syncthreads();
        stage(2 * kb + 3);
        {
            const uint32_t vA = sV + (uint32_t)(kb & 1) * 16384 + vrow;
#pragma unroll
            for (int kk = 0; kk < 2; kk++) {
                const uint32_t voff = ((uint32_t)((2 * kk + sgbit) ^ vq)) << 4;
#pragma unroll
                for (int p = 0; p < 16; p++) {
                    uint32_t vf[4];
                    ldsm4(vf, vA + p * 1024 + voff);
                    mma16h(Oac[2 * p],     pa[kk], vf[0], vf[1]);
                    mma16h(Oac[2 * p + 1], pa[kk], vf[2], vf[3]);
                }
            }
        }
    }

    // ---- epilogue: warp-local row sums, O/l, store ----
    lac0 += __shfl_xor_sync(0xffffffffu, lac0, 1);
    lac0 += __shfl_xor_sync(0xffffffffu, lac0, 2);
    lac1 += __shfl_xor_sync(0xffffffffu, lac1, 1);
    lac1 += __shfl_xor_sync(0xffffffffu, lac1, 2);
    const float inv0 = 1.f / lac0;
    const float inv1 = 1.f / lac1;
    const int r0 = q0 + rb + ty;
    float* o0 = out + ((size_t)(bb * 1024 + r0)) * 2304 + cc * 768 + hh * 256;
    float* o1 = o0 + (size_t)8 * 2304;
#pragma unroll
    for (int j = 0; j < 32; j++) {
        const int ccol = j * 8 + tx * 2;
        *(float2*)&o0[ccol] = make_float2(Oac[j][0] * inv0, Oac[j][1] * inv0);
        *(float2*)&o1[ccol] = make_float2(Oac[j][2] * inv1, Oac[j][3] * inv1);
    }
}

// ============================================================
extern "C" void kernel_launch(void* const* d_in, const int* in_sizes, int n_in,
                              void* d_out, int out_size)
{
    const float* x  = (const float*)d_in[0];
    const float* Wq = (const float*)d_in[1];
    const float* bq = (const float*)d_in[2];
    const float* Wk = (const float*)d_in[3];
    const float* bk = (const float*)d_in[4];
    const float* Wv = (const float*)d_in[5];
    const float* bv = (const float*)d_in[6];
    float* out = (float*)d_out;

    cudaFuncSetAttribute(qkv_mma,  cudaFuncAttributeMaxDynamicSharedMemorySize, QKV_SMEM);
    cudaFuncSetAttribute(attn_mma, cudaFuncAttributeMaxDynamicSharedMemorySize, ATT_SMEM);

    qkv_mma<<<dim3(16, 72, 3), 256, QKV_SMEM>>>(x, Wq, bq, Wk, bk, Wv, bv);
    attn_mma<<<dim3(8, 72), 256, ATT_SMEM>>>(out);
}